// round 5
// baseline (speedup 1.0000x reference)
#include <cuda_runtime.h>
#include <math.h>

// Problem dims (fixed by the reference)
#define B_  512
#define XD  768
#define YD  128
#define H2_ 512
#define NPART 16
#define KS1 4          // gemm1 K-splits (768/4 = 192)
#define KS2 4          // gemm2 K-splits (512/4 = 128)

typedef unsigned long long u64;

// Scratch (no allocations allowed -> __device__ globals)
__device__ float  g_H[2][KS1][B_ * H2_];   // gemm1 raw partials
__device__ float  g_Q[2][KS2][B_ * YD];    // gemm2 raw partials
__device__ double g_SyP [NPART][YD];
__device__ double g_Sy2P[NPART][YD];
__device__ double g_pos_row[B_];
__device__ double g_all_row[B_];
__device__ unsigned int g_ctr = 0;

// ---------------- f32x2 packed-FMA helpers (Blackwell FFMA2) ----------------
__device__ __forceinline__ u64 pack2(float lo, float hi) {
    u64 r; asm("mov.b64 %0, {%1, %2};" : "=l"(r) : "f"(lo), "f"(hi)); return r;
}
__device__ __forceinline__ void fma2(u64 &d, u64 a, u64 b) {
    asm("fma.rn.f32x2 %0, %1, %2, %0;" : "+l"(d) : "l"(a), "l"(b));
}
__device__ __forceinline__ float2 unpack2(u64 v) {
    float2 f; asm("mov.b64 {%0, %1}, %2;" : "=f"(f.x), "=f"(f.y) : "l"(v)); return f;
}

// ---------------------------------------------------------------------------
// Kernel A: blocks 0..511 = GEMM1 K-split partials (X@W1-slice, raw),
//           blocks 512..527 = y column stats.
// 64x64 tile, 128 thr, 4x8 micro via FFMA2. head=b&1, ks=(b>>1)&3, t=b>>3.
// ---------------------------------------------------------------------------
__global__ __launch_bounds__(128) void k_gemm1(
    const float* __restrict__ X,
    const float* __restrict__ Y,
    const float* __restrict__ Wmu,
    const float* __restrict__ Wlv)
{
    const int b = blockIdx.x;

    if (b >= 512) {
        // ---- ystats role ----
        const int p = b - 512;
        const int d = threadIdx.x;   // blockDim=128=YD
        const int j0 = p * (B_ / NPART);
        double sy0 = 0.0, sy1 = 0.0, sy20 = 0.0, sy21 = 0.0;
        #pragma unroll 4
        for (int j = j0; j < j0 + B_ / NPART; j += 2) {
            double v0 = (double)Y[j * YD + d];
            double v1 = (double)Y[(j + 1) * YD + d];
            sy0 += v0; sy20 = fma(v0, v0, sy20);
            sy1 += v1; sy21 = fma(v1, v1, sy21);
        }
        g_SyP [p][d] = sy0 + sy1;
        g_Sy2P[p][d] = sy20 + sy21;
        return;
    }

    // ---- GEMM1 partial role ----
    const int head = b & 1;
    const int ks   = (b >> 1) & 3;
    const int t    = b >> 3;             // 0..63
    const int n0   = (t & 7) * 64;
    const int m0   = (t >> 3) * 64;
    const float* W = head ? Wlv : Wmu;
    float*       P = g_H[head][ks];

    __shared__ __align__(16) u64   As2[16][66];  // [k][m] dup {a,a}, padded
    __shared__ __align__(16) float Bs [16][68];  // [k][n], padded

    const int tid = threadIdx.x;
    const int tx  = tid & 7;             // 8 col-groups of 8
    const int ty  = tid >> 3;            // 16 row-groups of 4

    const int arow = tid >> 1;           // 0..63
    const int ak   = (tid & 1) * 8;      // 0 or 8
    const int brow = tid >> 3;           // 0..15
    const int bcol = (tid & 7) * 8;      // 0..56

    const int kbase = ks * (XD / KS1);   // 192 per split
    const float* Xp = X + (m0 + arow) * XD + kbase + ak;
    const float* Wp = W + (kbase + brow) * H2_ + n0 + bcol;

    u64 acc[4][4] = {};

    float4 a_lo = *(const float4*)(Xp + 0);
    float4 a_hi = *(const float4*)(Xp + 4);
    float4 b_lo = *(const float4*)(Wp + 0);
    float4 b_hi = *(const float4*)(Wp + 4);

    const int k_iters = (XD / KS1) / 16;  // 12
    for (int it = 0; it < k_iters; it++) {
        As2[ak + 0][arow] = pack2(a_lo.x, a_lo.x);
        As2[ak + 1][arow] = pack2(a_lo.y, a_lo.y);
        As2[ak + 2][arow] = pack2(a_lo.z, a_lo.z);
        As2[ak + 3][arow] = pack2(a_lo.w, a_lo.w);
        As2[ak + 4][arow] = pack2(a_hi.x, a_hi.x);
        As2[ak + 5][arow] = pack2(a_hi.y, a_hi.y);
        As2[ak + 6][arow] = pack2(a_hi.z, a_hi.z);
        As2[ak + 7][arow] = pack2(a_hi.w, a_hi.w);
        *(float4*)(&Bs[brow][bcol + 0]) = b_lo;
        *(float4*)(&Bs[brow][bcol + 4]) = b_hi;
        __syncthreads();

        if (it + 1 < k_iters) {
            a_lo = *(const float4*)(Xp + (it + 1) * 16 + 0);
            a_hi = *(const float4*)(Xp + (it + 1) * 16 + 4);
            b_lo = *(const float4*)(Wp + (it + 1) * 16 * H2_ + 0);
            b_hi = *(const float4*)(Wp + (it + 1) * 16 * H2_ + 4);
        }

        #pragma unroll
        for (int kk = 0; kk < 16; kk++) {
            ulonglong2 a01 = *(const ulonglong2*)(&As2[kk][ty * 4 + 0]);
            ulonglong2 a23 = *(const ulonglong2*)(&As2[kk][ty * 4 + 2]);
            ulonglong2 b01 = *(const ulonglong2*)(&Bs[kk][tx * 8 + 0]);
            ulonglong2 b23 = *(const ulonglong2*)(&Bs[kk][tx * 8 + 4]);
            fma2(acc[0][0], a01.x, b01.x); fma2(acc[0][1], a01.x, b01.y);
            fma2(acc[0][2], a01.x, b23.x); fma2(acc[0][3], a01.x, b23.y);
            fma2(acc[1][0], a01.y, b01.x); fma2(acc[1][1], a01.y, b01.y);
            fma2(acc[1][2], a01.y, b23.x); fma2(acc[1][3], a01.y, b23.y);
            fma2(acc[2][0], a23.x, b01.x); fma2(acc[2][1], a23.x, b01.y);
            fma2(acc[2][2], a23.x, b23.x); fma2(acc[2][3], a23.x, b23.y);
            fma2(acc[3][0], a23.y, b01.x); fma2(acc[3][1], a23.y, b01.y);
            fma2(acc[3][2], a23.y, b23.x); fma2(acc[3][3], a23.y, b23.y);
        }
        __syncthreads();
    }

    const int col = n0 + tx * 8;
    #pragma unroll
    for (int i = 0; i < 4; i++) {
        int row = m0 + ty * 4 + i;
        float2 c0 = unpack2(acc[i][0]);
        float2 c1 = unpack2(acc[i][1]);
        float2 c2 = unpack2(acc[i][2]);
        float2 c3 = unpack2(acc[i][3]);
        float4 o0 = {c0.x, c0.y, c1.x, c1.y};
        float4 o1 = {c2.x, c2.y, c3.x, c3.y};
        *(float4*)(P + row * H2_ + col + 0) = o0;
        *(float4*)(P + row * H2_ + col + 4) = o1;
    }
}

// ---------------------------------------------------------------------------
// GEMM2 partials: Q[head][ks] = relu(sum_j H[head][j] + b1) @ W2-slice (raw).
// 64x64 tile, 128 thr, 4x8 micro. grid (2, 8, 8): z = head*4 + ks.
// ---------------------------------------------------------------------------
__global__ __launch_bounds__(128) void k_gemm2(
    const float* __restrict__ b1mu, const float* __restrict__ b1lv,
    const float* __restrict__ W2mu, const float* __restrict__ W2lv)
{
    const int  head = blockIdx.z >> 2;
    const int  ks   = blockIdx.z & 3;
    const float* Hb = &g_H[head][0][0];
    const float* b1 = head ? b1lv : b1mu;
    const float* W  = head ? W2lv : W2mu;
    float*       Q  = g_Q[head][ks];

    __shared__ __align__(16) u64   As2[16][66];
    __shared__ __align__(16) float Bs [16][68];

    const int tid = threadIdx.x;
    const int tx  = tid & 7;
    const int ty  = tid >> 3;
    const int m0  = blockIdx.y * 64;
    const int n0  = blockIdx.x * 64;

    const int arow = tid >> 1;
    const int ak   = (tid & 1) * 8;
    const int brow = tid >> 3;
    const int bcol = (tid & 7) * 8;

    const int kbase = ks * (H2_ / KS2);  // 128 per split
    const int abase = (m0 + arow) * H2_ + kbase + ak;
    const float* Wp = W + (kbase + brow) * YD + n0 + bcol;
    const size_t HS = (size_t)B_ * H2_;

    u64 acc[4][4] = {};

    const int k_iters = (H2_ / KS2) / 16;  // 8
    for (int it = 0; it < k_iters; it++) {
        // A fragment: sum 4 gemm1 partials + bias, relu
        {
            int off = abase + it * 16;
            float4 s_lo = *(const float4*)(b1 + kbase + ak + it * 16 + 0);
            float4 s_hi = *(const float4*)(b1 + kbase + ak + it * 16 + 4);
            #pragma unroll
            for (int j = 0; j < KS1; j++) {
                float4 p_lo = *(const float4*)(Hb + j * HS + off + 0);
                float4 p_hi = *(const float4*)(Hb + j * HS + off + 4);
                s_lo.x += p_lo.x; s_lo.y += p_lo.y; s_lo.z += p_lo.z; s_lo.w += p_lo.w;
                s_hi.x += p_hi.x; s_hi.y += p_hi.y; s_hi.z += p_hi.z; s_hi.w += p_hi.w;
            }
            float v0 = fmaxf(s_lo.x, 0.0f), v1 = fmaxf(s_lo.y, 0.0f);
            float v2 = fmaxf(s_lo.z, 0.0f), v3 = fmaxf(s_lo.w, 0.0f);
            float v4 = fmaxf(s_hi.x, 0.0f), v5 = fmaxf(s_hi.y, 0.0f);
            float v6 = fmaxf(s_hi.z, 0.0f), v7 = fmaxf(s_hi.w, 0.0f);
            As2[ak + 0][arow] = pack2(v0, v0);
            As2[ak + 1][arow] = pack2(v1, v1);
            As2[ak + 2][arow] = pack2(v2, v2);
            As2[ak + 3][arow] = pack2(v3, v3);
            As2[ak + 4][arow] = pack2(v4, v4);
            As2[ak + 5][arow] = pack2(v5, v5);
            As2[ak + 6][arow] = pack2(v6, v6);
            As2[ak + 7][arow] = pack2(v7, v7);
        }
        {
            float4 b_lo = *(const float4*)(Wp + it * 16 * YD + 0);
            float4 b_hi = *(const float4*)(Wp + it * 16 * YD + 4);
            *(float4*)(&Bs[brow][bcol + 0]) = b_lo;
            *(float4*)(&Bs[brow][bcol + 4]) = b_hi;
        }
        __syncthreads();

        #pragma unroll
        for (int kk = 0; kk < 16; kk++) {
            ulonglong2 a01 = *(const ulonglong2*)(&As2[kk][ty * 4 + 0]);
            ulonglong2 a23 = *(const ulonglong2*)(&As2[kk][ty * 4 + 2]);
            ulonglong2 b01 = *(const ulonglong2*)(&Bs[kk][tx * 8 + 0]);
            ulonglong2 b23 = *(const ulonglong2*)(&Bs[kk][tx * 8 + 4]);
            fma2(acc[0][0], a01.x, b01.x); fma2(acc[0][1], a01.x, b01.y);
            fma2(acc[0][2], a01.x, b23.x); fma2(acc[0][3], a01.x, b23.y);
            fma2(acc[1][0], a01.y, b01.x); fma2(acc[1][1], a01.y, b01.y);
            fma2(acc[1][2], a01.y, b23.x); fma2(acc[1][3], a01.y, b23.y);
            fma2(acc[2][0], a23.x, b01.x); fma2(acc[2][1], a23.x, b01.y);
            fma2(acc[2][2], a23.x, b23.x); fma2(acc[2][3], a23.x, b23.y);
            fma2(acc[3][0], a23.y, b01.x); fma2(acc[3][1], a23.y, b01.y);
            fma2(acc[3][2], a23.y, b23.x); fma2(acc[3][3], a23.y, b23.y);
        }
        __syncthreads();
    }

    const int col = n0 + tx * 8;
    #pragma unroll
    for (int i = 0; i < 4; i++) {
        int row = m0 + ty * 4 + i;
        float2 c0 = unpack2(acc[i][0]);
        float2 c1 = unpack2(acc[i][1]);
        float2 c2 = unpack2(acc[i][2]);
        float2 c3 = unpack2(acc[i][3]);
        float4 o0 = {c0.x, c0.y, c1.x, c1.y};
        float4 o1 = {c2.x, c2.y, c3.x, c3.y};
        *(float4*)(Q + row * YD + col + 0) = o0;
        *(float4*)(Q + row * YD + col + 4) = o1;
    }
}

// ---------------------------------------------------------------------------
// Kernel C: epilogue (bias+tanh+exp) + per-row reductions + final scalar.
// grid 128 x 128 thr; one warp per row (4 rows/block), last-block ticket.
//  mu = sum_j Qmu_j + b2mu;  lv = tanh(sum_j Qlv_j + b2lv);  iv = exp(-lv)
//  pos_i = sum_d [-0.5 (mu-y)^2 iv - 0.5 lv]
//  all_i = sum_d [-0.5 iv (Sy2 - 2 mu Sy + 512 mu^2) - 256 lv]
// negative == all_probs exactly in fp32 (511 + e^-20 == 511; log(B-1) cancels)
// ---------------------------------------------------------------------------
__global__ __launch_bounds__(128) void k_rows_final(
    const float* __restrict__ Y,
    const float* __restrict__ b2mu, const float* __restrict__ b2lv,
    float* __restrict__ out, int out_size)
{
    __shared__ double sSy[YD];
    __shared__ double sSy2[YD];
    __shared__ bool s_last;

    const int tid = threadIdx.x;

    {
        double s = 0.0, s2 = 0.0;
        #pragma unroll
        for (int p = 0; p < NPART; p++) { s += g_SyP[p][tid]; s2 += g_Sy2P[p][tid]; }
        sSy[tid] = s; sSy2[tid] = s2;
    }
    __syncthreads();

    const int lane = tid & 31;
    const int wid  = tid >> 5;
    const int i    = blockIdx.x * 4 + wid;

    double pos = 0.0, row = 0.0;
    #pragma unroll
    for (int q = 0; q < 4; q++) {
        int d = q * 32 + lane;
        int idx = i * YD + d;
        float muf = b2mu[d];
        float sf  = b2lv[d];
        #pragma unroll
        for (int j = 0; j < KS2; j++) {
            muf += g_Q[0][j][idx];
            sf  += g_Q[1][j][idx];
        }
        float lvf = tanhf(sf);
        float ivf = expf(-lvf);
        float yf  = Y[idx];

        float dmy = muf - yf;
        pos += (double)fmaf(-0.5f * dmy * dmy, ivf, -0.5f * lvf);

        double mu = (double)muf;
        double tq = fma(mu, fma(512.0, mu, -2.0 * sSy[d]), sSy2[d]);
        row = fma(-0.5 * (double)ivf, tq, row);
        row = fma(-256.0, (double)lvf, row);
    }
    #pragma unroll
    for (int off = 16; off > 0; off >>= 1) {
        pos += __shfl_down_sync(0xffffffffu, pos, off);
        row += __shfl_down_sync(0xffffffffu, row, off);
    }
    if (lane == 0) {
        g_pos_row[i] = pos;
        g_all_row[i] = row;
        __threadfence();
    }
    __syncthreads();

    if (tid == 0) {
        unsigned old = atomicAdd(&g_ctr, 1u);
        s_last = (old == gridDim.x - 1);
    }
    __syncthreads();
    if (!s_last) return;

    // ---- last block: deterministic final reduce over 512 rows ----
    double p0 = 0.0, a0 = 0.0;
    #pragma unroll
    for (int j = tid; j < B_; j += 128) {
        p0 += g_pos_row[j];
        a0 += g_all_row[j];
    }
    sSy[tid]  = p0;
    sSy2[tid] = a0;
    __syncthreads();
    #pragma unroll
    for (int s = 64; s > 0; s >>= 1) {
        if (tid < s) { sSy[tid] += sSy[tid + s]; sSy2[tid] += sSy2[tid + s]; }
        __syncthreads();
    }
    if (tid == 0) {
        double res = sSy[0] / 512.0 - sSy2[0] / (512.0 * 512.0);
        out[0] = (float)res;
        g_ctr = 0;  // reset for next graph replay
    }
    for (int k = tid + 1; k < out_size; k += 128) out[k] = 0.0f;
}

// ---------------------------------------------------------------------------
extern "C" void kernel_launch(void* const* d_in, const int* in_sizes, int n_in,
                              void* d_out, int out_size)
{
    const float* x   = (const float*)d_in[0];
    const float* y   = (const float*)d_in[1];
    const float* w1m = (const float*)d_in[2];
    const float* b1m = (const float*)d_in[3];
    const float* w2m = (const float*)d_in[4];
    const float* b2m = (const float*)d_in[5];
    const float* w1l = (const float*)d_in[6];
    const float* b1l = (const float*)d_in[7];
    const float* w2l = (const float*)d_in[8];
    const float* b2l = (const float*)d_in[9];

    k_gemm1<<<512 + NPART, 128>>>(x, y, w1m, w1l);

    dim3 g2(YD / 64, B_ / 64, 8);    // (2, 8, 8) = 128 blocks
    k_gemm2<<<g2, 128>>>(b1m, b1l, w2m, w2l);

    k_rows_final<<<B_ / 4, 128>>>(y, b2m, b2l, (float*)d_out, out_size);
}